// round 4
// baseline (speedup 1.0000x reference)
#include <cuda_runtime.h>

#define DM 768
#define TD 2304          // 3*DM
#define NBATCH 2
#define CTX 2048
#define NHEADS 12
#define HD 64

// Scratch for z = x @ W^T + b : [NBATCH*CTX, TD] = 37.7 MB (static device global; no alloc)
__device__ float g_z[(size_t)NBATCH * CTX * TD];

// ---------------------------------------------------------------------------
// Kernel 1: QKV projection GEMM. z[m,e] = sum_k x[m,k]*W[e,k] + b[e]
// M=4096, N=2304, K=768. 128x128 block tile, 8x8 per-thread, BK=8, 256 threads.
// Double-buffered smem: one __syncthreads per k-step, LDG overlapped with FFMA.
// ---------------------------------------------------------------------------
__global__ __launch_bounds__(256) void qkv_gemm_k(
    const float* __restrict__ x, const float* __restrict__ W,
    const float* __restrict__ bias)
{
    __shared__ float As[2][8][132];   // [buf][k][m], padded
    __shared__ float Bs[2][8][132];   // [buf][k][e]

    const int tid = threadIdx.x;
    const int m0 = blockIdx.y * 128;
    const int n0 = blockIdx.x * 128;
    const int ty = tid >> 4;       // 0..15
    const int tx = tid & 15;       // 0..15

    float acc[8][8];
#pragma unroll
    for (int i = 0; i < 8; i++)
#pragma unroll
        for (int j = 0; j < 8; j++) acc[i][j] = 0.f;

    const int lrow  = tid >> 1;    // 0..127
    const int lpart = tid & 1;     // 0..1
    const float* ap = x + (size_t)(m0 + lrow) * DM + lpart * 4;
    const float* bp = W + (size_t)(n0 + lrow) * DM + lpart * 4;

    // Prologue: load k-tile 0 into buffer 0
    {
        const float4 av = *(const float4*)(ap);
        const float4 bv = *(const float4*)(bp);
        As[0][lpart * 4 + 0][lrow] = av.x;
        As[0][lpart * 4 + 1][lrow] = av.y;
        As[0][lpart * 4 + 2][lrow] = av.z;
        As[0][lpart * 4 + 3][lrow] = av.w;
        Bs[0][lpart * 4 + 0][lrow] = bv.x;
        Bs[0][lpart * 4 + 1][lrow] = bv.y;
        Bs[0][lpart * 4 + 2][lrow] = bv.z;
        Bs[0][lpart * 4 + 3][lrow] = bv.w;
    }
    __syncthreads();

    int buf = 0;
    for (int k0 = 0; k0 < DM; k0 += 8) {
        const bool has_next = (k0 + 8) < DM;
        float4 av, bv;
        if (has_next) {           // issue next tile's loads early (overlap with FFMAs)
            av = *(const float4*)(ap + k0 + 8);
            bv = *(const float4*)(bp + k0 + 8);
        }

#pragma unroll
        for (int kk = 0; kk < 8; kk++) {
            const float4 a0 = *(const float4*)&As[buf][kk][ty * 8];
            const float4 a1 = *(const float4*)&As[buf][kk][ty * 8 + 4];
            const float4 b0 = *(const float4*)&Bs[buf][kk][tx * 8];
            const float4 b1 = *(const float4*)&Bs[buf][kk][tx * 8 + 4];
            const float a[8] = {a0.x, a0.y, a0.z, a0.w, a1.x, a1.y, a1.z, a1.w};
            const float b[8] = {b0.x, b0.y, b0.z, b0.w, b1.x, b1.y, b1.z, b1.w};
#pragma unroll
            for (int i = 0; i < 8; i++)
#pragma unroll
                for (int j = 0; j < 8; j++) acc[i][j] += a[i] * b[j];
        }

        if (has_next) {
            const int nb = buf ^ 1;
            As[nb][lpart * 4 + 0][lrow] = av.x;
            As[nb][lpart * 4 + 1][lrow] = av.y;
            As[nb][lpart * 4 + 2][lrow] = av.z;
            As[nb][lpart * 4 + 3][lrow] = av.w;
            Bs[nb][lpart * 4 + 0][lrow] = bv.x;
            Bs[nb][lpart * 4 + 1][lrow] = bv.y;
            Bs[nb][lpart * 4 + 2][lrow] = bv.z;
            Bs[nb][lpart * 4 + 3][lrow] = bv.w;
            __syncthreads();
            buf = nb;
        }
    }

    // Epilogue: add bias, store via float4 (coalesced)
#pragma unroll
    for (int i = 0; i < 8; i++) {
        const size_t row = (size_t)(m0 + ty * 8 + i) * TD + n0 + tx * 8;
        float4 r0, r1;
        r0.x = acc[i][0] + bias[n0 + tx * 8 + 0];
        r0.y = acc[i][1] + bias[n0 + tx * 8 + 1];
        r0.z = acc[i][2] + bias[n0 + tx * 8 + 2];
        r0.w = acc[i][3] + bias[n0 + tx * 8 + 3];
        r1.x = acc[i][4] + bias[n0 + tx * 8 + 4];
        r1.y = acc[i][5] + bias[n0 + tx * 8 + 5];
        r1.z = acc[i][6] + bias[n0 + tx * 8 + 6];
        r1.w = acc[i][7] + bias[n0 + tx * 8 + 7];
        *(float4*)&g_z[row]     = r0;
        *(float4*)&g_z[row + 4] = r1;
    }
}

// ---------------------------------------------------------------------------
// Kernel 2: causal multi-head attention (flash style, online softmax).
// One CTA per (n, h, 64-row Q tile). 64x64 KV tiles. 256 threads.
// z layout per row: [K(0:768) | Q(768:1536) | V(1536:2304)]
// ---------------------------------------------------------------------------
__global__ __launch_bounds__(256) void attn_k(float* __restrict__ out)
{
    extern __shared__ float sm[];
    float* Qs   = sm;                  // [64][65]
    float* Ks   = sm + 64 * 65;        // [64][65]
    float* Vs   = sm + 2 * 64 * 65;    // [64][65]
    float* Ss   = sm + 3 * 64 * 65;    // [64][65]  (scores, then P in place)
    float* mrow = sm + 4 * 64 * 65;    // [64]
    float* lrow = mrow + 64;           // [64]
    float* frow = lrow + 64;           // [64]

    const int tid = threadIdx.x;
    const int qt  = (int)gridDim.x - 1 - (int)blockIdx.x;  // big tiles launch first
    const int h   = blockIdx.y;
    const int n   = blockIdx.z;

    const float* zb = g_z + (size_t)n * CTX * TD;
    const int kof = h * HD;
    const int qof = DM + h * HD;
    const int vof = 2 * DM + h * HD;

    // Load Q tile
    for (int idx = tid; idx < 64 * 64; idx += 256) {
        const int r = idx >> 6, d = idx & 63;
        Qs[r * 65 + d] = zb[(size_t)(qt * 64 + r) * TD + qof + d];
    }
    if (tid < 64) { mrow[tid] = -1e30f; lrow[tid] = 0.f; }
    __syncthreads();

    const int ty = tid >> 4, tx = tid & 15;
    const int r0 = ty * 4, c0 = tx * 4;

    float o[4][4];
#pragma unroll
    for (int i = 0; i < 4; i++)
#pragma unroll
        for (int j = 0; j < 4; j++) o[i][j] = 0.f;

    const float scale = 0.03608439182435161f;  // 1/sqrt(768)

    for (int jt = 0; jt <= qt; jt++) {
        // Load K,V tiles
        for (int idx = tid; idx < 64 * 64; idx += 256) {
            const int r = idx >> 6, d = idx & 63;
            const size_t base = (size_t)(jt * 64 + r) * TD;
            Ks[r * 65 + d] = zb[base + kof + d];
            Vs[r * 65 + d] = zb[base + vof + d];
        }
        __syncthreads();

        // S = (Q K^T) * scale, with causal mask on diagonal tile
        float s[4][4];
#pragma unroll
        for (int i = 0; i < 4; i++)
#pragma unroll
            for (int j = 0; j < 4; j++) s[i][j] = 0.f;
#pragma unroll 8
        for (int kk = 0; kk < 64; kk++) {
            float a[4], b[4];
#pragma unroll
            for (int i = 0; i < 4; i++) a[i] = Qs[(r0 + i) * 65 + kk];
#pragma unroll
            for (int j = 0; j < 4; j++) b[j] = Ks[(c0 + j) * 65 + kk];
#pragma unroll
            for (int i = 0; i < 4; i++)
#pragma unroll
                for (int j = 0; j < 4; j++) s[i][j] += a[i] * b[j];
        }
        const bool diag = (jt == qt);
#pragma unroll
        for (int i = 0; i < 4; i++)
#pragma unroll
            for (int j = 0; j < 4; j++) {
                float v = s[i][j] * scale;
                if (diag && (c0 + j) > (r0 + i)) v = -1e30f;
                Ss[(r0 + i) * 65 + c0 + j] = v;
            }
        __syncthreads();

        // Online softmax row update: 4 threads per row (quad shuffles)
        {
            const int row = tid >> 2, sub = tid & 3;
            float* srow = Ss + row * 65 + sub * 16;
            float lm = -1e30f;
#pragma unroll
            for (int c = 0; c < 16; c++) lm = fmaxf(lm, srow[c]);
            lm = fmaxf(lm, __shfl_xor_sync(0xffffffffu, lm, 1));
            lm = fmaxf(lm, __shfl_xor_sync(0xffffffffu, lm, 2));
            const float m_old = mrow[row];
            const float m_new = fmaxf(m_old, lm);
            float ls = 0.f;
#pragma unroll
            for (int c = 0; c < 16; c++) {
                const float p = __expf(srow[c] - m_new);
                srow[c] = p;
                ls += p;
            }
            ls += __shfl_xor_sync(0xffffffffu, ls, 1);
            ls += __shfl_xor_sync(0xffffffffu, ls, 2);
            if (sub == 0) {
                const float f = __expf(m_old - m_new);
                mrow[row] = m_new;
                lrow[row] = lrow[row] * f + ls;
                frow[row] = f;
            }
        }
        __syncthreads();

        // O = O * f + P @ V
        float fr[4];
#pragma unroll
        for (int i = 0; i < 4; i++) fr[i] = frow[r0 + i];
#pragma unroll
        for (int i = 0; i < 4; i++)
#pragma unroll
            for (int j = 0; j < 4; j++) o[i][j] *= fr[i];

#pragma unroll 8
        for (int c = 0; c < 64; c++) {
            float a[4], b[4];
#pragma unroll
            for (int i = 0; i < 4; i++) a[i] = Ss[(r0 + i) * 65 + c];
#pragma unroll
            for (int j = 0; j < 4; j++) b[j] = Vs[c * 65 + c0 + j];
#pragma unroll
            for (int i = 0; i < 4; i++)
#pragma unroll
                for (int j = 0; j < 4; j++) o[i][j] += a[i] * b[j];
        }
        __syncthreads();   // before next tile overwrites Ks/Vs/Ss
    }

    // Normalize and write output: out[n, c, h*64 + d]
    float inv[4];
#pragma unroll
    for (int i = 0; i < 4; i++) inv[i] = 1.f / lrow[r0 + i];
#pragma unroll
    for (int i = 0; i < 4; i++) {
        const size_t ob = ((size_t)n * CTX + qt * 64 + r0 + i) * DM + h * HD + c0;
#pragma unroll
        for (int j = 0; j < 4; j++) out[ob + j] = o[i][j] * inv[i];
    }
}

// ---------------------------------------------------------------------------
extern "C" void kernel_launch(void* const* d_in, const int* in_sizes, int n_in,
                              void* d_out, int out_size)
{
    (void)in_sizes; (void)n_in; (void)out_size;
    const float* x = (const float*)d_in[0];
    const float* W = (const float*)d_in[1];
    const float* b = (const float*)d_in[2];
    float* out = (float*)d_out;

    dim3 gg(TD / 128, (NBATCH * CTX) / 128);   // (18, 32)
    qkv_gemm_k<<<gg, 256>>>(x, W, b);

    const int smem = (4 * 64 * 65 + 3 * 64) * (int)sizeof(float);  // 67328 B
    cudaFuncSetAttribute(attn_k, cudaFuncAttributeMaxDynamicSharedMemorySize, smem);
    dim3 ga(CTX / 64, NHEADS, NBATCH);         // (32, 12, 2)
    attn_k<<<ga, 256, smem>>>(out);
}

// round 8
// speedup vs baseline: 1.0059x; 1.0059x over previous
#include <cuda_runtime.h>

#define DM 768
#define TD 2304          // 3*DM
#define NBATCH 2
#define CTX 2048
#define NHEADS 12
#define HD 64
#define PAD 68           // row stride (floats): mult of 4 (f4-aligned), ≡4 mod 32 (conflict-free @ 1-row lane stride)

// Scratch for z = x @ W^T + b : [NBATCH*CTX, TD] = 37.7 MB (static device global; no alloc)
__device__ float g_z[(size_t)NBATCH * CTX * TD];

// ---------------------------------------------------------------------------
// Kernel 1: QKV projection GEMM. z[m,e] = sum_k x[m,k]*W[e,k] + b[e]
// M=4096, N=2304, K=768. 128x128 block tile, 8x8 per-thread, BK=8, 256 threads.
// Double-buffered smem. (Unchanged from round-4: measured ~330us, near fp32 peak.)
// ---------------------------------------------------------------------------
__global__ __launch_bounds__(256) void qkv_gemm_k(
    const float* __restrict__ x, const float* __restrict__ W,
    const float* __restrict__ bias)
{
    __shared__ float As[2][8][132];
    __shared__ float Bs[2][8][132];

    const int tid = threadIdx.x;
    const int m0 = blockIdx.y * 128;
    const int n0 = blockIdx.x * 128;
    const int ty = tid >> 4;
    const int tx = tid & 15;

    float acc[8][8];
#pragma unroll
    for (int i = 0; i < 8; i++)
#pragma unroll
        for (int j = 0; j < 8; j++) acc[i][j] = 0.f;

    const int lrow  = tid >> 1;
    const int lpart = tid & 1;
    const float* ap = x + (size_t)(m0 + lrow) * DM + lpart * 4;
    const float* bp = W + (size_t)(n0 + lrow) * DM + lpart * 4;

    {
        const float4 av = *(const float4*)(ap);
        const float4 bv = *(const float4*)(bp);
        As[0][lpart * 4 + 0][lrow] = av.x;
        As[0][lpart * 4 + 1][lrow] = av.y;
        As[0][lpart * 4 + 2][lrow] = av.z;
        As[0][lpart * 4 + 3][lrow] = av.w;
        Bs[0][lpart * 4 + 0][lrow] = bv.x;
        Bs[0][lpart * 4 + 1][lrow] = bv.y;
        Bs[0][lpart * 4 + 2][lrow] = bv.z;
        Bs[0][lpart * 4 + 3][lrow] = bv.w;
    }
    __syncthreads();

    int buf = 0;
    for (int k0 = 0; k0 < DM; k0 += 8) {
        const bool has_next = (k0 + 8) < DM;
        float4 av, bv;
        if (has_next) {
            av = *(const float4*)(ap + k0 + 8);
            bv = *(const float4*)(bp + k0 + 8);
        }

#pragma unroll
        for (int kk = 0; kk < 8; kk++) {
            const float4 a0 = *(const float4*)&As[buf][kk][ty * 8];
            const float4 a1 = *(const float4*)&As[buf][kk][ty * 8 + 4];
            const float4 b0 = *(const float4*)&Bs[buf][kk][tx * 8];
            const float4 b1 = *(const float4*)&Bs[buf][kk][tx * 8 + 4];
            const float a[8] = {a0.x, a0.y, a0.z, a0.w, a1.x, a1.y, a1.z, a1.w};
            const float b[8] = {b0.x, b0.y, b0.z, b0.w, b1.x, b1.y, b1.z, b1.w};
#pragma unroll
            for (int i = 0; i < 8; i++)
#pragma unroll
                for (int j = 0; j < 8; j++) acc[i][j] += a[i] * b[j];
        }

        if (has_next) {
            const int nb = buf ^ 1;
            As[nb][lpart * 4 + 0][lrow] = av.x;
            As[nb][lpart * 4 + 1][lrow] = av.y;
            As[nb][lpart * 4 + 2][lrow] = av.z;
            As[nb][lpart * 4 + 3][lrow] = av.w;
            Bs[nb][lpart * 4 + 0][lrow] = bv.x;
            Bs[nb][lpart * 4 + 1][lrow] = bv.y;
            Bs[nb][lpart * 4 + 2][lrow] = bv.z;
            Bs[nb][lpart * 4 + 3][lrow] = bv.w;
            __syncthreads();
            buf = nb;
        }
    }

#pragma unroll
    for (int i = 0; i < 8; i++) {
        const size_t row = (size_t)(m0 + ty * 8 + i) * TD + n0 + tx * 8;
        float4 r0, r1;
        r0.x = acc[i][0] + bias[n0 + tx * 8 + 0];
        r0.y = acc[i][1] + bias[n0 + tx * 8 + 1];
        r0.z = acc[i][2] + bias[n0 + tx * 8 + 2];
        r0.w = acc[i][3] + bias[n0 + tx * 8 + 3];
        r1.x = acc[i][4] + bias[n0 + tx * 8 + 4];
        r1.y = acc[i][5] + bias[n0 + tx * 8 + 5];
        r1.z = acc[i][6] + bias[n0 + tx * 8 + 6];
        r1.w = acc[i][7] + bias[n0 + tx * 8 + 7];
        *(float4*)&g_z[row]     = r0;
        *(float4*)&g_z[row + 4] = r1;
    }
}

// ---------------------------------------------------------------------------
// Kernel 2: causal MHA, flash-style. Vectorized smem (float4 everywhere in the
// two GEMM loops). Thread tile: rows r_i = ty+16i, cols c_j = tx+16j (strided
// mapping => 1-row lane stride => conflict-free float4 LDS with PAD=68).
// V stored transposed in smem (VsT[d][c]) so PV vectorizes along c.
// ---------------------------------------------------------------------------
__global__ __launch_bounds__(256) void attn_k(float* __restrict__ out)
{
    extern __shared__ float sm[];
    float* Qs   = sm;                     // [64][PAD]  Q[r][d]
    float* Ks   = sm + 64 * PAD;          // [64][PAD]  K[c][d]
    float* VsT  = sm + 2 * 64 * PAD;      // [64][PAD]  V^T[d][c]
    float* Ss   = sm + 3 * 64 * PAD;      // [64][PAD]  S[r][c] -> P[r][c]
    float* mrow = sm + 4 * 64 * PAD;      // [64]
    float* lrow = mrow + 64;              // [64]
    float* frow = lrow + 64;              // [64]

    const int tid = threadIdx.x;
    const int qt  = (int)gridDim.x - 1 - (int)blockIdx.x;  // big tiles launch first
    const int h   = blockIdx.y;
    const int n   = blockIdx.z;

    const float* zb = g_z + (size_t)n * CTX * TD;
    const int kof = h * HD;
    const int qof = DM + h * HD;
    const int vof = 2 * DM + h * HD;

    const int lr = tid >> 4;          // loader row helper 0..15
    const int ld4 = (tid & 15) * 4;   // loader d-offset

    // Load Q tile (float4 gmem + float4 smem store)
    for (int r = lr; r < 64; r += 16) {
        const float4 v = *(const float4*)&zb[(size_t)(qt * 64 + r) * TD + qof + ld4];
        *(float4*)&Qs[r * PAD + ld4] = v;
    }
    if (tid < 64) { mrow[tid] = -1e30f; lrow[tid] = 0.f; }
    __syncthreads();

    const int ty = tid >> 4, tx = tid & 15;

    float o[4][4];
#pragma unroll
    for (int i = 0; i < 4; i++)
#pragma unroll
        for (int j = 0; j < 4; j++) o[i][j] = 0.f;

    const float scale = 0.03608439182435161f;  // 1/sqrt(768)

    for (int jt = 0; jt <= qt; jt++) {
        // Load K (natural) and V (transposed) tiles
        for (int r = lr; r < 64; r += 16) {
            const size_t base = (size_t)(jt * 64 + r) * TD;
            const float4 kv = *(const float4*)&zb[base + kof + ld4];
            *(float4*)&Ks[r * PAD + ld4] = kv;
            const float4 vv = *(const float4*)&zb[base + vof + ld4];
            VsT[(ld4 + 0) * PAD + r] = vv.x;
            VsT[(ld4 + 1) * PAD + r] = vv.y;
            VsT[(ld4 + 2) * PAD + r] = vv.z;
            VsT[(ld4 + 3) * PAD + r] = vv.w;
        }
        __syncthreads();

        // S = (Q K^T) * scale  — float4 along k
        float s[4][4];
#pragma unroll
        for (int i = 0; i < 4; i++)
#pragma unroll
            for (int j = 0; j < 4; j++) s[i][j] = 0.f;
#pragma unroll 4
        for (int kk = 0; kk < 64; kk += 4) {
            float4 a4[4], b4[4];
#pragma unroll
            for (int i = 0; i < 4; i++) a4[i] = *(const float4*)&Qs[(ty + 16 * i) * PAD + kk];
#pragma unroll
            for (int j = 0; j < 4; j++) b4[j] = *(const float4*)&Ks[(tx + 16 * j) * PAD + kk];
#pragma unroll
            for (int i = 0; i < 4; i++)
#pragma unroll
                for (int j = 0; j < 4; j++)
                    s[i][j] += a4[i].x * b4[j].x + a4[i].y * b4[j].y
                             + a4[i].z * b4[j].z + a4[i].w * b4[j].w;
        }
        const bool diag = (jt == qt);
#pragma unroll
        for (int i = 0; i < 4; i++) {
            const int ri = ty + 16 * i;
#pragma unroll
            for (int j = 0; j < 4; j++) {
                const int cj = tx + 16 * j;
                float v = s[i][j] * scale;
                if (diag && cj > ri) v = -1e30f;
                Ss[ri * PAD + cj] = v;
            }
        }
        __syncthreads();

        // Online softmax row update: 4 threads per row
        {
            const int row = tid >> 2, sub = tid & 3;
            float* srow = Ss + row * PAD + sub * 16;
            float lm = -1e30f;
#pragma unroll
            for (int c = 0; c < 16; c++) lm = fmaxf(lm, srow[c]);
            lm = fmaxf(lm, __shfl_xor_sync(0xffffffffu, lm, 1));
            lm = fmaxf(lm, __shfl_xor_sync(0xffffffffu, lm, 2));
            const float m_old = mrow[row];
            const float m_new = fmaxf(m_old, lm);
            float ls = 0.f;
#pragma unroll
            for (int c = 0; c < 16; c++) {
                const float p = __expf(srow[c] - m_new);
                srow[c] = p;
                ls += p;
            }
            ls += __shfl_xor_sync(0xffffffffu, ls, 1);
            ls += __shfl_xor_sync(0xffffffffu, ls, 2);
            if (sub == 0) {
                const float f = __expf(m_old - m_new);
                mrow[row] = m_new;
                lrow[row] = lrow[row] * f + ls;
                frow[row] = f;
            }
        }
        __syncthreads();

        // O = O * f + P @ V  — float4 along c (VsT rows are c-contiguous)
        float fr[4];
#pragma unroll
        for (int i = 0; i < 4; i++) fr[i] = frow[ty + 16 * i];
#pragma unroll
        for (int i = 0; i < 4; i++)
#pragma unroll
            for (int j = 0; j < 4; j++) o[i][j] *= fr[i];

#pragma unroll 4
        for (int c = 0; c < 64; c += 4) {
            float4 a4[4], b4[4];
#pragma unroll
            for (int i = 0; i < 4; i++) a4[i] = *(const float4*)&Ss[(ty + 16 * i) * PAD + c];
#pragma unroll
            for (int j = 0; j < 4; j++) b4[j] = *(const float4*)&VsT[(tx + 16 * j) * PAD + c];
#pragma unroll
            for (int i = 0; i < 4; i++)
#pragma unroll
                for (int j = 0; j < 4; j++)
                    o[i][j] += a4[i].x * b4[j].x + a4[i].y * b4[j].y
                             + a4[i].z * b4[j].z + a4[i].w * b4[j].w;
        }
        __syncthreads();   // before next tile overwrites Ks/VsT/Ss
    }

    // Normalize and write output: out[n, q, h*64 + d]
    float inv[4];
#pragma unroll
    for (int i = 0; i < 4; i++) inv[i] = 1.f / lrow[ty + 16 * i];
#pragma unroll
    for (int i = 0; i < 4; i++) {
        const size_t ob = ((size_t)n * CTX + qt * 64 + ty + 16 * i) * DM + h * HD;
#pragma unroll
        for (int j = 0; j < 4; j++) out[ob + tx + 16 * j] = o[i][j] * inv[i];
    }
}

// ---------------------------------------------------------------------------
extern "C" void kernel_launch(void* const* d_in, const int* in_sizes, int n_in,
                              void* d_out, int out_size)
{
    (void)in_sizes; (void)n_in; (void)out_size;
    const float* x = (const float*)d_in[0];
    const float* W = (const float*)d_in[1];
    const float* b = (const float*)d_in[2];
    float* out = (float*)d_out;

    dim3 gg(TD / 128, (NBATCH * CTX) / 128);   // (18, 32)
    qkv_gemm_k<<<gg, 256>>>(x, W, b);

    const int smem = (4 * 64 * PAD + 3 * 64) * (int)sizeof(float);  // 70400 B
    cudaFuncSetAttribute(attn_k, cudaFuncAttributeMaxDynamicSharedMemorySize, smem);
    dim3 ga(CTX / 64, NHEADS, NBATCH);         // (32, 12, 2)
    attn_k<<<ga, 256, smem>>>(out);
}

// round 11
// speedup vs baseline: 1.6044x; 1.5949x over previous
#include <cuda_runtime.h>
#include <cstdint>

#define DM 768
#define TD 2304          // 3*DM
#define NBATCH 2
#define CTX 2048
#define NHEADS 12
#define HD 64
#define WPAD 68          // Q/K/S row stride: frag bank = 4g+t (unique over warp) -> conflict-free
#define VPAD 72          // V row stride: frag bank = 8t+g (unique over warp) -> conflict-free

// Scratch for z = x @ W^T + b : [NBATCH*CTX, TD] = 37.7 MB (static device global; no alloc)
__device__ float g_z[(size_t)NBATCH * CTX * TD];

// ---------------------------------------------------------------------------
// tf32 helpers
// ---------------------------------------------------------------------------
__device__ __forceinline__ float tf32f(float x) {
    unsigned u;
    asm("cvt.rna.tf32.f32 %0, %1;" : "=r"(u) : "f"(x));
    return __uint_as_float(u);
}

__device__ __forceinline__ void mma_tf32(float c[4],
    uint32_t a0, uint32_t a1, uint32_t a2, uint32_t a3,
    uint32_t b0, uint32_t b1)
{
    asm volatile(
        "mma.sync.aligned.m16n8k8.row.col.f32.tf32.tf32.f32 "
        "{%0,%1,%2,%3}, {%4,%5,%6,%7}, {%8,%9}, {%0,%1,%2,%3};"
        : "+f"(c[0]), "+f"(c[1]), "+f"(c[2]), "+f"(c[3])
        : "r"(a0), "r"(a1), "r"(a2), "r"(a3), "r"(b0), "r"(b1));
}

// ---------------------------------------------------------------------------
// Kernel 1: QKV projection GEMM (unchanged from round-8: ~330us measured).
// ---------------------------------------------------------------------------
__global__ __launch_bounds__(256) void qkv_gemm_k(
    const float* __restrict__ x, const float* __restrict__ W,
    const float* __restrict__ bias)
{
    __shared__ float As[2][8][132];
    __shared__ float Bs[2][8][132];

    const int tid = threadIdx.x;
    const int m0 = blockIdx.y * 128;
    const int n0 = blockIdx.x * 128;
    const int ty = tid >> 4;
    const int tx = tid & 15;

    float acc[8][8];
#pragma unroll
    for (int i = 0; i < 8; i++)
#pragma unroll
        for (int j = 0; j < 8; j++) acc[i][j] = 0.f;

    const int lrow  = tid >> 1;
    const int lpart = tid & 1;
    const float* ap = x + (size_t)(m0 + lrow) * DM + lpart * 4;
    const float* bp = W + (size_t)(n0 + lrow) * DM + lpart * 4;

    {
        const float4 av = *(const float4*)(ap);
        const float4 bv = *(const float4*)(bp);
        As[0][lpart * 4 + 0][lrow] = av.x;
        As[0][lpart * 4 + 1][lrow] = av.y;
        As[0][lpart * 4 + 2][lrow] = av.z;
        As[0][lpart * 4 + 3][lrow] = av.w;
        Bs[0][lpart * 4 + 0][lrow] = bv.x;
        Bs[0][lpart * 4 + 1][lrow] = bv.y;
        Bs[0][lpart * 4 + 2][lrow] = bv.z;
        Bs[0][lpart * 4 + 3][lrow] = bv.w;
    }
    __syncthreads();

    int buf = 0;
    for (int k0 = 0; k0 < DM; k0 += 8) {
        const bool has_next = (k0 + 8) < DM;
        float4 av, bv;
        if (has_next) {
            av = *(const float4*)(ap + k0 + 8);
            bv = *(const float4*)(bp + k0 + 8);
        }

#pragma unroll
        for (int kk = 0; kk < 8; kk++) {
            const float4 a0 = *(const float4*)&As[buf][kk][ty * 8];
            const float4 a1 = *(const float4*)&As[buf][kk][ty * 8 + 4];
            const float4 b0 = *(const float4*)&Bs[buf][kk][tx * 8];
            const float4 b1 = *(const float4*)&Bs[buf][kk][tx * 8 + 4];
            const float a[8] = {a0.x, a0.y, a0.z, a0.w, a1.x, a1.y, a1.z, a1.w};
            const float b[8] = {b0.x, b0.y, b0.z, b0.w, b1.x, b1.y, b1.z, b1.w};
#pragma unroll
            for (int i = 0; i < 8; i++)
#pragma unroll
                for (int j = 0; j < 8; j++) acc[i][j] += a[i] * b[j];
        }

        if (has_next) {
            const int nb = buf ^ 1;
            As[nb][lpart * 4 + 0][lrow] = av.x;
            As[nb][lpart * 4 + 1][lrow] = av.y;
            As[nb][lpart * 4 + 2][lrow] = av.z;
            As[nb][lpart * 4 + 3][lrow] = av.w;
            Bs[nb][lpart * 4 + 0][lrow] = bv.x;
            Bs[nb][lpart * 4 + 1][lrow] = bv.y;
            Bs[nb][lpart * 4 + 2][lrow] = bv.z;
            Bs[nb][lpart * 4 + 3][lrow] = bv.w;
            __syncthreads();
            buf = nb;
        }
    }

#pragma unroll
    for (int i = 0; i < 8; i++) {
        const size_t row = (size_t)(m0 + ty * 8 + i) * TD + n0 + tx * 8;
        float4 r0, r1;
        r0.x = acc[i][0] + bias[n0 + tx * 8 + 0];
        r0.y = acc[i][1] + bias[n0 + tx * 8 + 1];
        r0.z = acc[i][2] + bias[n0 + tx * 8 + 2];
        r0.w = acc[i][3] + bias[n0 + tx * 8 + 3];
        r1.x = acc[i][4] + bias[n0 + tx * 8 + 4];
        r1.y = acc[i][5] + bias[n0 + tx * 8 + 5];
        r1.z = acc[i][6] + bias[n0 + tx * 8 + 6];
        r1.w = acc[i][7] + bias[n0 + tx * 8 + 7];
        *(float4*)&g_z[row]     = r0;
        *(float4*)&g_z[row + 4] = r1;
    }
}

// ---------------------------------------------------------------------------
// Kernel 2: causal MHA via tf32 mma.sync (m16n8k8). 8 warps, 64x64 tiles.
// Warp (wr=wid>>1, wc=wid&1) owns S/O block rows 16*wr, cols 32*wc.
// Q/K/V converted to tf32 at smem-store time; P converted post-softmax so the
// l-normalizer sums the same converted p values the PV mma consumes.
// ---------------------------------------------------------------------------
__global__ __launch_bounds__(256) void attn_k(float* __restrict__ out)
{
    extern __shared__ float sm[];
    float* Qs   = sm;                       // [64][WPAD] tf32 bits
    float* Ks   = Qs + 64 * WPAD;           // [64][WPAD] tf32 bits
    float* Ss   = Ks + 64 * WPAD;           // [64][WPAD] fp32 scores -> tf32 p
    float* Vs   = Ss + 64 * WPAD;           // [64][VPAD] tf32 bits (natural [kv][d])
    float* mrow = Vs + 64 * VPAD;           // [64]
    float* lrow = mrow + 64;                // [64]
    float* frow = lrow + 64;                // [64]

    const int tid = threadIdx.x;
    const int qt  = (int)gridDim.x - 1 - (int)blockIdx.x;  // big tiles first
    const int h   = blockIdx.y;
    const int n   = blockIdx.z;

    const float* zb = g_z + (size_t)n * CTX * TD;
    const int kof = h * HD;
    const int qof = DM + h * HD;
    const int vof = 2 * DM + h * HD;

    const int lr  = tid >> 4;         // loader row 0..15
    const int ld4 = (tid & 15) * 4;   // loader d-offset

    // Load Q tile, converting to tf32
    for (int r = lr; r < 64; r += 16) {
        const float4 v = *(const float4*)&zb[(size_t)(qt * 64 + r) * TD + qof + ld4];
        float4 tv = make_float4(tf32f(v.x), tf32f(v.y), tf32f(v.z), tf32f(v.w));
        *(float4*)&Qs[r * WPAD + ld4] = tv;
    }
    if (tid < 64) { mrow[tid] = -1e30f; lrow[tid] = 0.f; }
    __syncthreads();

    const int lane = tid & 31, wid = tid >> 5;
    const int g = lane >> 2, t = lane & 3;
    const int wr = wid >> 1, wc = wid & 1;
    const int arow = 16 * wr + g;          // fragment row (lo); hi = +8

    float oacc[4][4];
#pragma unroll
    for (int nt = 0; nt < 4; nt++)
#pragma unroll
        for (int e = 0; e < 4; e++) oacc[nt][e] = 0.f;

    const float scale = 0.03608439182435161f;  // 1/sqrt(768)

    for (int jt = 0; jt <= qt; jt++) {
        // Load K and V tiles (tf32-converted)
        for (int r = lr; r < 64; r += 16) {
            const size_t base = (size_t)(jt * 64 + r) * TD;
            const float4 kv = *(const float4*)&zb[base + kof + ld4];
            *(float4*)&Ks[r * WPAD + ld4] =
                make_float4(tf32f(kv.x), tf32f(kv.y), tf32f(kv.z), tf32f(kv.w));
            const float4 vv = *(const float4*)&zb[base + vof + ld4];
            *(float4*)&Vs[r * VPAD + ld4] =
                make_float4(tf32f(vv.x), tf32f(vv.y), tf32f(vv.z), tf32f(vv.w));
        }
        __syncthreads();

        // ---- S = Q K^T via mma (k = head dim, 8 chunks) ----
        float sacc[4][4];
#pragma unroll
        for (int nt = 0; nt < 4; nt++)
#pragma unroll
            for (int e = 0; e < 4; e++) sacc[nt][e] = 0.f;

#pragma unroll
        for (int kc = 0; kc < 8; kc++) {
            const int k0 = kc * 8;
            const uint32_t a0 = __float_as_uint(Qs[arow * WPAD + k0 + t]);
            const uint32_t a1 = __float_as_uint(Qs[(arow + 8) * WPAD + k0 + t]);
            const uint32_t a2 = __float_as_uint(Qs[arow * WPAD + k0 + t + 4]);
            const uint32_t a3 = __float_as_uint(Qs[(arow + 8) * WPAD + k0 + t + 4]);
#pragma unroll
            for (int nt = 0; nt < 4; nt++) {
                const int brow = 32 * wc + 8 * nt + g;   // kv index (S column)
                const uint32_t b0 = __float_as_uint(Ks[brow * WPAD + k0 + t]);
                const uint32_t b1 = __float_as_uint(Ks[brow * WPAD + k0 + t + 4]);
                mma_tf32(sacc[nt], a0, a1, a2, a3, b0, b1);
            }
        }

        // Scale + causal mask + store S (fp32) to smem
        const bool diag = (jt == qt);
#pragma unroll
        for (int nt = 0; nt < 4; nt++) {
            const int col0 = 32 * wc + 8 * nt + 2 * t;
            float v00 = sacc[nt][0] * scale, v01 = sacc[nt][1] * scale;
            float v10 = sacc[nt][2] * scale, v11 = sacc[nt][3] * scale;
            if (diag) {
                if (col0     > arow)     v00 = -1e30f;
                if (col0 + 1 > arow)     v01 = -1e30f;
                if (col0     > arow + 8) v10 = -1e30f;
                if (col0 + 1 > arow + 8) v11 = -1e30f;
            }
            Ss[arow * WPAD + col0]           = v00;
            Ss[arow * WPAD + col0 + 1]       = v01;
            Ss[(arow + 8) * WPAD + col0]     = v10;
            Ss[(arow + 8) * WPAD + col0 + 1] = v11;
        }
        __syncthreads();

        // ---- Online softmax: 4 threads per row; store tf32-converted p ----
        {
            const int row = tid >> 2, sub = tid & 3;
            float* srow = Ss + row * WPAD + sub * 16;
            float lm = -1e30f;
#pragma unroll
            for (int c = 0; c < 16; c++) lm = fmaxf(lm, srow[c]);
            lm = fmaxf(lm, __shfl_xor_sync(0xffffffffu, lm, 1));
            lm = fmaxf(lm, __shfl_xor_sync(0xffffffffu, lm, 2));
            const float m_old = mrow[row];
            const float m_new = fmaxf(m_old, lm);
            float ls = 0.f;
#pragma unroll
            for (int c = 0; c < 16; c++) {
                const float p = tf32f(__expf(srow[c] - m_new));
                srow[c] = p;          // tf32 bits, ready for PV mma
                ls += p;              // normalizer matches numerator exactly
            }
            ls += __shfl_xor_sync(0xffffffffu, ls, 1);
            ls += __shfl_xor_sync(0xffffffffu, ls, 2);
            if (sub == 0) {
                const float f = __expf(m_old - m_new);
                mrow[row] = m_new;
                lrow[row] = lrow[row] * f + ls;
                frow[row] = f;
            }
        }
        __syncthreads();

        // ---- O = O*f + P V via mma (k = kv, 8 chunks) ----
        const float fLo = frow[arow], fHi = frow[arow + 8];
#pragma unroll
        for (int nt = 0; nt < 4; nt++) {
            oacc[nt][0] *= fLo; oacc[nt][1] *= fLo;
            oacc[nt][2] *= fHi; oacc[nt][3] *= fHi;
        }
#pragma unroll
        for (int kc = 0; kc < 8; kc++) {
            const int k0 = kc * 8;
            const uint32_t a0 = __float_as_uint(Ss[arow * WPAD + k0 + t]);
            const uint32_t a1 = __float_as_uint(Ss[(arow + 8) * WPAD + k0 + t]);
            const uint32_t a2 = __float_as_uint(Ss[arow * WPAD + k0 + t + 4]);
            const uint32_t a3 = __float_as_uint(Ss[(arow + 8) * WPAD + k0 + t + 4]);
#pragma unroll
            for (int nt = 0; nt < 4; nt++) {
                const int ncol = 32 * wc + 8 * nt + g;   // output d index
                const uint32_t b0 = __float_as_uint(Vs[(k0 + t) * VPAD + ncol]);
                const uint32_t b1 = __float_as_uint(Vs[(k0 + t + 4) * VPAD + ncol]);
                mma_tf32(oacc[nt], a0, a1, a2, a3, b0, b1);
            }
        }
        __syncthreads();   // before next tile overwrites Ks/Vs/Ss
    }

    // Epilogue: normalize, write out[n, q, h*64 + d]
    const float invLo = 1.f / lrow[arow];
    const float invHi = 1.f / lrow[arow + 8];
    const size_t basLo = ((size_t)n * CTX + qt * 64 + arow) * DM + h * HD;
    const size_t basHi = basLo + (size_t)8 * DM;
#pragma unroll
    for (int nt = 0; nt < 4; nt++) {
        const int col0 = 32 * wc + 8 * nt + 2 * t;
        out[basLo + col0]     = oacc[nt][0] * invLo;
        out[basLo + col0 + 1] = oacc[nt][1] * invLo;
        out[basHi + col0]     = oacc[nt][2] * invHi;
        out[basHi + col0 + 1] = oacc[nt][3] * invHi;
    }
}

// ---------------------------------------------------------------------------
extern "C" void kernel_launch(void* const* d_in, const int* in_sizes, int n_in,
                              void* d_out, int out_size)
{
    (void)in_sizes; (void)n_in; (void)out_size;
    const float* x = (const float*)d_in[0];
    const float* W = (const float*)d_in[1];
    const float* b = (const float*)d_in[2];
    float* out = (float*)d_out;

    dim3 gg(TD / 128, (NBATCH * CTX) / 128);   // (18, 32)
    qkv_gemm_k<<<gg, 256>>>(x, W, b);

    const int smem = (3 * 64 * WPAD + 64 * VPAD + 3 * 64) * (int)sizeof(float);  // 71424 B
    cudaFuncSetAttribute(attn_k, cudaFuncAttributeMaxDynamicSharedMemorySize, smem);
    dim3 ga(CTX / 64, NHEADS, NBATCH);         // (32, 12, 2)
    attn_k<<<ga, 256, smem>>>(out);
}